// round 5
// baseline (speedup 1.0000x reference)
#include <cuda_runtime.h>
#include <cuda_bf16.h>
#include <cuda_fp16.h>

// ---------------------------------------------------------------------------
// GAT 3-layer + PairNorm. N=50000 nodes, E=800000 edges (+N self loops).
//   - CSR-by-dst built per call (int atomics + decoupled 3-kernel scan).
//   - Per layer: tiled FP32 GEMM (f32x2 FMA) with fused PairNorm+ReLU on the
//     A-load and fused attention-coef epilogue, writing fp16 features ->
//     single-pass softmax aggregation (warp-per-node, fp16 gathers, no float
//     atomics) with fused column-sum -> tiny per-row-scale kernel.
//   - Layer 3 fuses head-mean + bias, writes d_out directly.
// ---------------------------------------------------------------------------

#define MAXN 50000
#define MAXE 1000000   // E + N with margin

__device__ __align__(16) __half g_xh[MAXN * 128];
__device__ __align__(16) float g_agg[MAXN * 128];
__device__ __align__(16) float g_als[MAXN * 2];
__device__ __align__(16) float g_ald[MAXN * 2];
__device__ __align__(16) float g_scale[MAXN];
__device__ __align__(16) float g_cs[2][128];
__device__ int g_cnt[MAXN + 1];
__device__ int g_off[MAXN + 1];
__device__ int g_cur[MAXN];
__device__ int g_csr[MAXE];
__device__ int g_bsum[256];
__device__ int g_bpre[256];
__device__ int g_is64;

// ---------------------------------------------------------------------------
// edge_index dtype probe
// ---------------------------------------------------------------------------
__global__ void detect_kernel(const void* ei, int N) {
    const long long* p = (const long long*)ei;
    long long v = p[threadIdx.x];
    int ok = (v >= 0 && v < (long long)N);
    unsigned b = __ballot_sync(0xffffffffu, ok);
    if (threadIdx.x == 0) g_is64 = (b == 0xffffffffu) ? 1 : 0;
}

__device__ __forceinline__ int edge_val(const void* ei, int idx) {
    if (g_is64) return (int)((const long long*)ei)[idx];
    return ((const int*)ei)[idx];
}

__global__ void zero_int_kernel(int* p, int n) {
    int i = blockIdx.x * blockDim.x + threadIdx.x;
    if (i < n) p[i] = 0;
}

__global__ void hist_kernel(const void* ei, int E, int Etot, int* cnt) {
    int e = blockIdx.x * blockDim.x + threadIdx.x;
    if (e >= Etot) return;
    int dst = (e < E) ? edge_val(ei, E + e) : (e - E);
    atomicAdd(&cnt[dst], 1);
}

// ---------------------------------------------------------------------------
// Decoupled scan
// ---------------------------------------------------------------------------
__global__ void scan_bsum_kernel(const int* __restrict__ cnt, int* __restrict__ bsum, int n) {
    int t = threadIdx.x;
    int i = blockIdx.x * 256 + t;
    int v = (i < n) ? cnt[i] : 0;
#pragma unroll
    for (int o = 16; o > 0; o >>= 1) v += __shfl_down_sync(0xffffffffu, v, o);
    __shared__ int ws[8];
    if ((t & 31) == 0) ws[t >> 5] = v;
    __syncthreads();
    if (t == 0) {
        int s = 0;
#pragma unroll
        for (int w = 0; w < 8; w++) s += ws[w];
        bsum[blockIdx.x] = s;
    }
}

__global__ void scan_bscan_kernel(const int* __restrict__ bsum, int* __restrict__ bpre,
                                  int* __restrict__ off, int nb, int n) {
    __shared__ int sm[256];
    int t = threadIdx.x;
    int v = (t < nb) ? bsum[t] : 0;
    sm[t] = v;
    __syncthreads();
#pragma unroll
    for (int d = 1; d < 256; d <<= 1) {
        int x = (t >= d) ? sm[t - d] : 0;
        __syncthreads();
        sm[t] += x;
        __syncthreads();
    }
    if (t < nb) bpre[t] = sm[t] - v;
    if (t == 255) off[n] = sm[255];
}

__global__ void scan_write_kernel(const int* __restrict__ cnt, const int* __restrict__ bpre,
                                  int* __restrict__ off, int* __restrict__ cur, int n) {
    __shared__ int sm[256];
    int t = threadIdx.x;
    int i = blockIdx.x * 256 + t;
    int v = (i < n) ? cnt[i] : 0;
    sm[t] = v;
    __syncthreads();
#pragma unroll
    for (int d = 1; d < 256; d <<= 1) {
        int x = (t >= d) ? sm[t - d] : 0;
        __syncthreads();
        sm[t] += x;
        __syncthreads();
    }
    if (i < n) {
        int o = bpre[blockIdx.x] + sm[t] - v;
        off[i] = o;
        cur[i] = o;
    }
}

__global__ void scatter_kernel(const void* ei, int E, int Etot, int* cur, int* csr) {
    int e = blockIdx.x * blockDim.x + threadIdx.x;
    if (e >= Etot) return;
    int src, dst;
    if (e < E) { src = edge_val(ei, e); dst = edge_val(ei, E + e); }
    else       { src = dst = e - E; }
    int pos = atomicAdd(&cur[dst], 1);
    csr[pos] = src;
}

// ---------------------------------------------------------------------------
// GEMM: C[N x OW](fp16) = act(A[N x 128]) * W[128 x OW], f32x2 packed FMA.
// If PN: act(v) = relu((v - mean[c]) * scale[row]) fused into A-tile load.
// Thread (tx,ty) owns column PAIRS (2tx, 2tx+1) + j*2*CT, j=0..3 (8 cols).
// Pairs j=0,1 are head 0; j=2,3 head 1. Fused epilogue: als/ald per (row,head).
// Zeroes cs_zero[0:128) from block 0 (next layer's column-sum buffer).
// ---------------------------------------------------------------------------
template <int OW, bool PN>
__global__ void __launch_bounds__(256)
gemm_attn_kernel(const float* __restrict__ A,
                 const float* __restrict__ mean_cs, const float* __restrict__ rscale,
                 const float* __restrict__ W,
                 const float* __restrict__ asrc, const float* __restrict__ adst,
                 __half* __restrict__ C,
                 float* __restrict__ als, float* __restrict__ ald,
                 float* __restrict__ cs_zero, int N) {
    constexpr int BK = 32;
    constexpr int BM = 64;
    constexpr int CT = OW / 8;        // threads along cols
    constexpr int RT = 256 / CT;      // threads along rows
    constexpr int RPT = BM / RT;      // rows per thread
    __shared__ float As[BM][BK + 1];
    __shared__ float Ws[BK][OW];
    __shared__ float Ms[128];         // column means (PN)
    __shared__ float Ss[BM];          // row scales (PN)
    __shared__ float Ps0[BM][CT], Pd0[BM][CT];
    __shared__ float Ps1[BM][CT], Pd1[BM][CT];
    int t = threadIdx.x;
    int tx = t % CT, ty = t / CT;
    int row0 = blockIdx.x * BM;

    if (cs_zero && blockIdx.x == 0 && t < 128) cs_zero[t] = 0.f;
    if (PN) {
        if (t < 128) Ms[t] = mean_cs[t] * (1.0f / (float)N);
        if (t >= 128 && t < 128 + BM) {
            int gr = row0 + t - 128;
            Ss[t - 128] = (gr < N) ? rscale[gr] : 0.f;
        }
        __syncthreads();
    }

    unsigned long long acc2[RPT][4];
#pragma unroll
    for (int r = 0; r < RPT; r++)
#pragma unroll
        for (int j = 0; j < 4; j++) acc2[r][j] = 0ULL;

    for (int k0 = 0; k0 < 128; k0 += BK) {
        for (int i = t; i < BM * BK; i += 256) {
            int r = i / BK, c = i % BK;
            int gr = row0 + r;
            float v = (gr < N) ? A[(size_t)gr * 128 + k0 + c] : 0.f;
            if (PN) v = fmaxf((v - Ms[k0 + c]) * Ss[r], 0.f);
            As[r][c] = v;
        }
        for (int i = t; i < BK * OW; i += 256) {
            int r = i / OW, c = i % OW;
            Ws[r][c] = W[(k0 + r) * OW + c];
        }
        __syncthreads();
#pragma unroll
        for (int kk = 0; kk < BK; kk++) {
            unsigned long long wv2[4];
#pragma unroll
            for (int j = 0; j < 4; j++)
                wv2[j] = *(const unsigned long long*)&Ws[kk][2 * tx + j * 2 * CT];
#pragma unroll
            for (int r = 0; r < RPT; r++) {
                float av = As[ty * RPT + r][kk];
                unsigned long long av2;
                asm("mov.b64 %0, {%1, %1};" : "=l"(av2) : "f"(av));
#pragma unroll
                for (int j = 0; j < 4; j++)
                    asm("fma.rn.f32x2 %0, %1, %2, %0;" : "+l"(acc2[r][j]) : "l"(av2), "l"(wv2[j]));
            }
        }
        __syncthreads();
    }

    float2 av[4], bv[4];
#pragma unroll
    for (int j = 0; j < 4; j++) {
        av[j] = ((const float2*)asrc)[tx + j * CT];
        bv[j] = ((const float2*)adst)[tx + j * CT];
    }

#pragma unroll
    for (int r = 0; r < RPT; r++) {
        int row = ty * RPT + r;
        int gr = row0 + row;
        float s0 = 0.f, d0 = 0.f, s1 = 0.f, d1 = 0.f;
        __half2 c2[4];
#pragma unroll
        for (int j = 0; j < 4; j++) {
            float lo, hi;
            asm("mov.b64 {%0, %1}, %2;" : "=f"(lo), "=f"(hi) : "l"(acc2[r][j]));
            c2[j] = __float22half2_rn(make_float2(lo, hi));
            if (j < 2) {
                s0 = fmaf(lo, av[j].x, fmaf(hi, av[j].y, s0));
                d0 = fmaf(lo, bv[j].x, fmaf(hi, bv[j].y, d0));
            } else {
                s1 = fmaf(lo, av[j].x, fmaf(hi, av[j].y, s1));
                d1 = fmaf(lo, bv[j].x, fmaf(hi, bv[j].y, d1));
            }
        }
        Ps0[row][tx] = s0; Pd0[row][tx] = d0;
        Ps1[row][tx] = s1; Pd1[row][tx] = d1;
        if (gr < N) {
#pragma unroll
            for (int j = 0; j < 4; j++)
                ((__half2*)&C[(size_t)gr * OW])[tx + j * CT] = c2[j];
        }
    }
    __syncthreads();
    if (t < BM * 2) {
        int row = t >> 1, h = t & 1;
        int gr = row0 + row;
        if (gr < N) {
            float s = 0.f, d = 0.f;
#pragma unroll
            for (int k = 0; k < CT; k++) {
                s += h ? Ps1[row][k] : Ps0[row][k];
                d += h ? Pd1[row][k] : Pd0[row][k];
            }
            als[gr * 2 + h] = s;
            ald[gr * 2 + h] = d;
        }
    }
}

__device__ __forceinline__ float lrelu(float x) { return fmaxf(x, 0.2f * x); }

// ---------------------------------------------------------------------------
// Single-pass softmax aggregation over fp16 features. Warp (or sub-warp)
// per destination node; fused column-sum (smem staging + 128 REDG).
// ---------------------------------------------------------------------------
template <int HD, bool FINAL>
__global__ void __launch_bounds__(256)
aggr_kernel(const __half* __restrict__ xh,
            const float* __restrict__ als, const float* __restrict__ ald,
            const int* __restrict__ off, const int* __restrict__ csr,
            const float* __restrict__ bias,
            float* __restrict__ out, float* __restrict__ cs, int N) {
    constexpr int D = HD / 2;
    constexpr int L = HD / 4;          // lanes per node (32 or 8)
    constexpr int NPW = 32 / L;        // nodes per warp (1 or 4)
    int wib = threadIdx.x >> 5;
    int wid = blockIdx.x * 8 + wib;
    int lane = threadIdx.x & 31;
    int lig = lane % L;
    int nreq = wid * NPW + lane / L;
    bool valid = nreq < N;
    int n = valid ? nreq : (N - 1);

    float2 ad = ((const float2*)ald)[n];
    int st = off[n], en = off[n + 1];

    int head = (lig * 4) / D;
    float s0 = 0.f, s1 = 0.f;
    float4 acc = make_float4(0.f, 0.f, 0.f, 0.f);
    const uint2* x8 = (const uint2*)xh;   // 4 halves per element
#pragma unroll 4
    for (int i = st; i < en; i++) {
        int s = csr[i];
        float2 as = ((const float2*)als)[s];
        float w0 = __expf(lrelu(as.x + ad.x));
        float w1 = __expf(lrelu(as.y + ad.y));
        s0 += w0; s1 += w1;
        float w = head ? w1 : w0;
        uint2 u = x8[(size_t)s * L + lig];
        float2 f0 = __half22float2(*(__half2*)&u.x);
        float2 f1 = __half22float2(*(__half2*)&u.y);
        acc.x = fmaf(w, f0.x, acc.x);
        acc.y = fmaf(w, f0.y, acc.y);
        acc.z = fmaf(w, f1.x, acc.z);
        acc.w = fmaf(w, f1.y, acc.w);
    }
    float inv = 1.0f / (head ? s1 : s0);
    acc.x *= inv; acc.y *= inv; acc.z *= inv; acc.w *= inv;

    if (FINAL) {
        float ox = __shfl_down_sync(0xffffffffu, acc.x, 4);
        float oy = __shfl_down_sync(0xffffffffu, acc.y, 4);
        float oz = __shfl_down_sync(0xffffffffu, acc.z, 4);
        float ow = __shfl_down_sync(0xffffffffu, acc.w, 4);
        if (valid && lig < 4) {
            float4 r;
            r.x = 0.5f * (acc.x + ox) + bias[lig * 4 + 0];
            r.y = 0.5f * (acc.y + oy) + bias[lig * 4 + 1];
            r.z = 0.5f * (acc.z + oz) + bias[lig * 4 + 2];
            r.w = 0.5f * (acc.w + ow) + bias[lig * 4 + 3];
            ((float4*)out)[(size_t)n * 4 + lig] = r;
        }
    } else {
        if (valid) ((float4*)out)[(size_t)n * L + lig] = acc;
        __shared__ float csm[8][128];
        float4 a = valid ? acc : make_float4(0.f, 0.f, 0.f, 0.f);
        ((float4*)csm[wib])[lig] = a;
        __syncthreads();
        int t = threadIdx.x;
        if (t < 128) {
            float s = 0.f;
#pragma unroll
            for (int w = 0; w < 8; w++) s += csm[w][t];
            atomicAdd(&cs[t], s);
        }
    }
}

// ---------------------------------------------------------------------------
// Per-row PairNorm scale: scale[n] = 1/(eps + ||row - mean||)
// ---------------------------------------------------------------------------
__global__ void pnscale_kernel(const float* __restrict__ in, const float* __restrict__ cs,
                               float* __restrict__ scale, int N) {
    int wid = (blockIdx.x * blockDim.x + threadIdx.x) >> 5;
    int lane = threadIdx.x & 31;
    if (wid >= N) return;
    float invN = 1.0f / (float)N;
    float4 m = ((const float4*)cs)[lane];
    float4 v = ((const float4*)in)[(size_t)wid * 32 + lane];
    v.x -= m.x * invN; v.y -= m.y * invN; v.z -= m.z * invN; v.w -= m.w * invN;
    float n2 = v.x * v.x + v.y * v.y + v.z * v.z + v.w * v.w;
#pragma unroll
    for (int o = 16; o > 0; o >>= 1) n2 += __shfl_xor_sync(0xffffffffu, n2, o);
    if (lane == 0) scale[wid] = 1.0f / (1e-5f + sqrtf(n2));
}

// ---------------------------------------------------------------------------
extern "C" void kernel_launch(void* const* d_in, const int* in_sizes, int n_in,
                              void* d_out, int out_size) {
    const float* x   = (const float*)d_in[0];
    const void*  ei  = d_in[1];
    const float* W1  = (const float*)d_in[2];
    const float* as1 = (const float*)d_in[3];
    const float* ad1 = (const float*)d_in[4];
    const float* W2  = (const float*)d_in[6];
    const float* as2 = (const float*)d_in[7];
    const float* ad2 = (const float*)d_in[8];
    const float* W3  = (const float*)d_in[10];
    const float* as3 = (const float*)d_in[11];
    const float* ad3 = (const float*)d_in[12];
    const float* b3  = (const float*)d_in[13];

    int N = in_sizes[0] / 128;
    int E = in_sizes[1] / 2;
    int Etot = E + N;

    __half* xh;
    float *agg, *als, *ald, *scl, *cs;
    int *cnt, *off, *cur, *csr, *bsum, *bpre;
    cudaGetSymbolAddress((void**)&xh, g_xh);
    cudaGetSymbolAddress((void**)&agg, g_agg);
    cudaGetSymbolAddress((void**)&als, g_als);
    cudaGetSymbolAddress((void**)&ald, g_ald);
    cudaGetSymbolAddress((void**)&scl, g_scale);
    cudaGetSymbolAddress((void**)&cs, g_cs);
    cudaGetSymbolAddress((void**)&cnt, g_cnt);
    cudaGetSymbolAddress((void**)&off, g_off);
    cudaGetSymbolAddress((void**)&cur, g_cur);
    cudaGetSymbolAddress((void**)&csr, g_csr);
    cudaGetSymbolAddress((void**)&bsum, g_bsum);
    cudaGetSymbolAddress((void**)&bpre, g_bpre);
    float* cs0 = cs;
    float* cs1 = cs + 128;

    const int TB = 256;
    int ewarp_blocks  = (N + 7) / 8;
    int ewarp_blocks4 = (N / 4 + 7) / 8;
    int gemm_blocks   = (N + 63) / 64;
    int nb1 = (N + 255) / 256;

    // ---- CSR build (shared by all 3 layers) ----
    detect_kernel<<<1, 32>>>(ei, N);
    zero_int_kernel<<<(N + TB - 1) / TB, TB>>>(cnt, N);
    hist_kernel<<<(Etot + TB - 1) / TB, TB>>>(ei, E, Etot, cnt);
    scan_bsum_kernel<<<nb1, 256>>>(cnt, bsum, N);
    scan_bscan_kernel<<<1, 256>>>(bsum, bpre, off, nb1, N);
    scan_write_kernel<<<nb1, 256>>>(cnt, bpre, off, cur, N);
    scatter_kernel<<<(Etot + TB - 1) / TB, TB>>>(ei, E, Etot, cur, csr);

    // ---- layer 1 ----
    gemm_attn_kernel<128, false><<<gemm_blocks, TB>>>(x, nullptr, nullptr, W1, as1, ad1,
                                                      xh, als, ald, cs0, N);
    aggr_kernel<128, false><<<ewarp_blocks, TB>>>(xh, als, ald, off, csr, nullptr, agg, cs0, N);
    pnscale_kernel<<<ewarp_blocks, TB>>>(agg, cs0, scl, N);

    // ---- layer 2 (PairNorm+ReLU fused into A-load) ----
    gemm_attn_kernel<128, true><<<gemm_blocks, TB>>>(agg, cs0, scl, W2, as2, ad2,
                                                     xh, als, ald, cs1, N);
    aggr_kernel<128, false><<<ewarp_blocks, TB>>>(xh, als, ald, off, csr, nullptr, agg, cs1, N);
    pnscale_kernel<<<ewarp_blocks, TB>>>(agg, cs1, scl, N);

    // ---- layer 3 (writes d_out with head-mean + bias) ----
    gemm_attn_kernel<32, true><<<gemm_blocks, TB>>>(agg, cs1, scl, W3, as3, ad3,
                                                    xh, als, ald, nullptr, N);
    aggr_kernel<32, true><<<ewarp_blocks4, TB>>>(xh, als, ald, off, csr, b3,
                                                 (float*)d_out, nullptr, N);
}